// round 11
// baseline (speedup 1.0000x reference)
#include <cuda_runtime.h>
#include <cstdint>

#define BN 8
#define CC 192
#define CQ 32
#define NN 16384
#define EPSV 1e-6f

typedef unsigned long long u64;

__device__ __forceinline__ u64 pk2(float lo, float hi) {
    u64 r; asm("mov.b64 %0,{%1,%2};" : "=l"(r) : "f"(lo), "f"(hi)); return r;
}
__device__ __forceinline__ void upk2(float& lo, float& hi, u64 v) {
    asm("mov.b64 {%0,%1},%2;" : "=f"(lo), "=f"(hi) : "l"(v));
}
__device__ __forceinline__ u64 fma2(u64 a, u64 b, u64 c) {
    u64 d; asm("fma.rn.f32x2 %0,%1,%2,%3;" : "=l"(d) : "l"(a), "l"(b), "l"(c)); return d;
}
__device__ __forceinline__ u64 mul2(u64 a, u64 b) {
    u64 d; asm("mul.rn.f32x2 %0,%1,%2;" : "=l"(d) : "l"(a), "l"(b)); return d;
}
__device__ __forceinline__ u64 add2(u64 a, u64 b) {
    u64 d; asm("add.rn.f32x2 %0,%1,%2;" : "=l"(d) : "l"(a), "l"(b)); return d;
}

__device__ __forceinline__ float to_tf32(float v) {
    float r; asm("cvt.rna.tf32.f32 %0, %1;" : "=f"(r) : "f"(v)); return r;
}

// D(16x8) += A(16x8,row) * B(8x8,col), tf32 inputs (b32 regs), f32 accum.
__device__ __forceinline__ void mma_tf32(float* d, const uint32_t* a,
                                         const uint32_t* b) {
    asm volatile(
        "mma.sync.aligned.m16n8k8.row.col.f32.tf32.tf32.f32 "
        "{%0,%1,%2,%3}, {%4,%5,%6,%7}, {%8,%9}, {%0,%1,%2,%3};"
        : "+f"(d[0]), "+f"(d[1]), "+f"(d[2]), "+f"(d[3])
        : "r"(a[0]), "r"(a[1]), "r"(a[2]), "r"(a[3]), "r"(b[0]), "r"(b[1]));
}

// Scratch (device globals: no allocation allowed)
__device__ float g_Qn[BN*CQ*NN];
__device__ float g_Kn[BN*CQ*NN];
__device__ float g_Ksum[BN*CQ];
__device__ float g_xsum[BN*CC];
__device__ float g_M1[BN*CQ*CC];
__device__ float g_mat[BN*CQ*CC];
__device__ float g_vsum[BN*CC];

__global__ void zero_kernel() {
    int i = blockIdx.x * blockDim.x + threadIdx.x;
    int stride = gridDim.x * blockDim.x;
    for (int j = i; j < BN*CQ; j += stride) g_Ksum[j] = 0.f;
    for (int j = i; j < BN*CC; j += stride) { g_xsum[j] = 0.f; g_vsum[j] = 0.f; }
    for (int j = i; j < BN*CQ*CC; j += stride) { g_M1[j] = 0.f; g_mat[j] = 0.f; }
}

// ---------------------------------------------------------------------------
// Q/K projection + L2 norm via mma.sync tf32 (3-term split, ~fp32 accurate).
// A = [Wq;Wk] (64 x 192) in smem as uint2{hi,lo} tf32 bit patterns, layout
// whl[k][row] with row-pitch 68 uint2 (bank-conflict-free fragment loads).
// B = x1 fragments straight from gmem (each element read exactly once).
// Block 256 = 8 warps; warp w owns 16 n (two 8-n strips); block n-tile 128.
// Grid (NN/128, BN). smem 104448 B -> occ 2.
// ---------------------------------------------------------------------------
__global__ void __launch_bounds__(256, 1) qk_kernel(
    const float* __restrict__ x1,
    const float* __restrict__ Wq, const float* __restrict__ bq,
    const float* __restrict__ Wk, const float* __restrict__ bk)
{
    extern __shared__ uint2 whl[];   // [192][68] row-pitch, entries {hi,lo}

    int tid = threadIdx.x;
    int bb  = blockIdx.y;
    int nb  = blockIdx.x * 128;

    // stage W split into tf32 hi/lo (coalesced gmem read, 8-way-conflict STS)
    for (int i = tid; i < 64*CC; i += 256) {
        int row = i / CC, k = i % CC;
        float w = (row < CQ) ? Wq[row*CC + k] : Wk[(row-CQ)*CC + k];
        float hi = to_tf32(w);
        float lo = to_tf32(w - hi);
        whl[k*68 + row] = make_uint2(__float_as_uint(hi), __float_as_uint(lo));
    }
    __syncthreads();

    int w  = tid >> 5;          // warp 0..7
    int ln = tid & 31;
    int g  = ln >> 2;           // group 0..7
    int la = ln & 3;            // thread-in-group 0..3
    int nwarp = nb + w*16;      // warp's first n

    float d[2][4][4];           // [strip][m-tile][reg]
#pragma unroll
    for (int s = 0; s < 2; s++)
#pragma unroll
        for (int t = 0; t < 4; t++)
#pragma unroll
            for (int j = 0; j < 4; j++) d[s][t][j] = 0.f;

    const float* xbase = x1 + (size_t)(bb*CC)*NN + nwarp + g;

    // prologue: B loads for k-step 0
    float cb0[2], cb1[2];
#pragma unroll
    for (int s = 0; s < 2; s++) {
        const float* xp = xbase + (size_t)la*NN + s*8;
        cb0[s] = xp[0];
        cb1[s] = xp[(size_t)4*NN];
    }

    for (int ks = 0; ks < 24; ks++) {
        int k0 = ks*8;
        // prefetch B for next k-step
        float nb0[2], nb1[2];
        if (ks + 1 < 24) {
            const float* xr = xbase + (size_t)(k0 + 8 + la)*NN;
#pragma unroll
            for (int s = 0; s < 2; s++) {
                nb0[s] = xr[s*8];
                nb1[s] = xr[(size_t)4*NN + s*8];
            }
        }

        // A fragments (hi+lo from packed uint2)
        uint32_t ahi[4][4], alo[4][4];
#pragma unroll
        for (int t = 0; t < 4; t++) {
            int r0 = g + 16*t, r1 = r0 + 8;
            uint2 v0 = whl[(k0+la)*68 + r0];
            uint2 v1 = whl[(k0+la)*68 + r1];
            uint2 v2 = whl[(k0+la+4)*68 + r0];
            uint2 v3 = whl[(k0+la+4)*68 + r1];
            ahi[t][0] = v0.x; alo[t][0] = v0.y;
            ahi[t][1] = v1.x; alo[t][1] = v1.y;
            ahi[t][2] = v2.x; alo[t][2] = v2.y;
            ahi[t][3] = v3.x; alo[t][3] = v3.y;
        }

#pragma unroll
        for (int s = 0; s < 2; s++) {
            float h0 = to_tf32(cb0[s]), l0f = to_tf32(cb0[s] - h0);
            float h1 = to_tf32(cb1[s]), l1f = to_tf32(cb1[s] - h1);
            uint32_t bh[2] = { __float_as_uint(h0), __float_as_uint(h1) };
            uint32_t bl[2] = { __float_as_uint(l0f), __float_as_uint(l1f) };
#pragma unroll
            for (int t = 0; t < 4; t++) {
                mma_tf32(d[s][t], ahi[t], bh);
                mma_tf32(d[s][t], alo[t], bh);
                mma_tf32(d[s][t], ahi[t], bl);
            }
        }
#pragma unroll
        for (int s = 0; s < 2; s++) { cb0[s] = nb0[s]; cb1[s] = nb1[s]; }
    }

    // bias (pre-normalization)
#pragma unroll
    for (int t = 0; t < 4; t++) {
        int r0 = g + 16*t, r1 = r0 + 8;
        float bias0 = (r0 < CQ) ? __ldg(&bq[r0]) : __ldg(&bk[r0-CQ]);
        float bias1 = (r1 < CQ) ? __ldg(&bq[r1]) : __ldg(&bk[r1-CQ]);
#pragma unroll
        for (int s = 0; s < 2; s++) {
            d[s][t][0] += bias0; d[s][t][1] += bias0;
            d[s][t][2] += bias1; d[s][t][3] += bias1;
        }
    }

    // column sums of squares: Q over tiles 0,1; K over tiles 2,3
    float qs0[2], qs1[2], ks0[2], ks1[2];
#pragma unroll
    for (int s = 0; s < 2; s++) {
        qs0[s] = d[s][0][0]*d[s][0][0] + d[s][0][2]*d[s][0][2]
               + d[s][1][0]*d[s][1][0] + d[s][1][2]*d[s][1][2];
        qs1[s] = d[s][0][1]*d[s][0][1] + d[s][0][3]*d[s][0][3]
               + d[s][1][1]*d[s][1][1] + d[s][1][3]*d[s][1][3];
        ks0[s] = d[s][2][0]*d[s][2][0] + d[s][2][2]*d[s][2][2]
               + d[s][3][0]*d[s][3][0] + d[s][3][2]*d[s][3][2];
        ks1[s] = d[s][2][1]*d[s][2][1] + d[s][2][3]*d[s][2][3]
               + d[s][3][1]*d[s][3][1] + d[s][3][3]*d[s][3][3];
    }
#pragma unroll
    for (int o = 4; o <= 16; o <<= 1) {
#pragma unroll
        for (int s = 0; s < 2; s++) {
            qs0[s] += __shfl_xor_sync(0xffffffffu, qs0[s], o);
            qs1[s] += __shfl_xor_sync(0xffffffffu, qs1[s], o);
            ks0[s] += __shfl_xor_sync(0xffffffffu, ks0[s], o);
            ks1[s] += __shfl_xor_sync(0xffffffffu, ks1[s], o);
        }
    }

    // normalize + store; accumulate K row sums
    float krow[4];   // rows g, g+8 (t=2), g+16, g+24 (t=3)
#pragma unroll
    for (int j = 0; j < 4; j++) krow[j] = 0.f;

#pragma unroll
    for (int s = 0; s < 2; s++) {
        float iq0 = rsqrtf(qs0[s]), iq1 = rsqrtf(qs1[s]);
        float ik0 = rsqrtf(ks0[s]), ik1 = rsqrtf(ks1[s]);
        int ncol = nwarp + s*8 + la*2;
#pragma unroll
        for (int t = 0; t < 2; t++) {   // Q tiles
            int m = g + 16*t;
            float2 v0 = make_float2(d[s][t][0]*iq0, d[s][t][1]*iq1);
            float2 v1 = make_float2(d[s][t][2]*iq0, d[s][t][3]*iq1);
            *(float2*)(g_Qn + (size_t)(bb*CQ + m)*NN + ncol)     = v0;
            *(float2*)(g_Qn + (size_t)(bb*CQ + m + 8)*NN + ncol) = v1;
        }
#pragma unroll
        for (int t = 2; t < 4; t++) {   // K tiles
            int m = g + 16*(t-2);
            float c0 = d[s][t][0]*ik0, c1 = d[s][t][1]*ik1;
            float c2 = d[s][t][2]*ik0, c3 = d[s][t][3]*ik1;
            *(float2*)(g_Kn + (size_t)(bb*CQ + m)*NN + ncol)     = make_float2(c0, c1);
            *(float2*)(g_Kn + (size_t)(bb*CQ + m + 8)*NN + ncol) = make_float2(c2, c3);
            krow[(t-2)*2]   += c0 + c1;
            krow[(t-2)*2+1] += c2 + c3;
        }
    }
    // reduce row sums over la (bits 0,1), then atomics from la==0
#pragma unroll
    for (int o = 1; o <= 2; o <<= 1)
#pragma unroll
        for (int j = 0; j < 4; j++)
            krow[j] += __shfl_xor_sync(0xffffffffu, krow[j], o);
    if (la == 0) {
        atomicAdd(&g_Ksum[bb*CQ + g],      krow[0]);
        atomicAdd(&g_Ksum[bb*CQ + g + 8],  krow[1]);
        atomicAdd(&g_Ksum[bb*CQ + g + 16], krow[2]);
        atomicAdd(&g_Ksum[bb*CQ + g + 24], krow[3]);
    }
}

// ---------------------------------------------------------------------------
// M1[b,m,p] = sum_n Kn[b,m,n]*x[b,p,n]; xsum[b,p] = sum_n x[b,p,n]
// Block 192: tid = jh*96 + mh*48 + pq. Thread tile: 16 m x 4 p, packed over p.
// ---------------------------------------------------------------------------
__global__ void __launch_bounds__(192, 2) m1_kernel(const float* __restrict__ x)
{
    __shared__ float xs[32*196];      // [j][p], pad 196
    __shared__ u64 kst2[32*34];       // [j][m] duplicated {k,k}, pad 34

    int tid = threadIdx.x;
    int b = blockIdx.y;
    int nbase = blockIdx.x * 512;

    int jh = tid / 96;
    int rr = tid % 96;
    int mh = rr / 48;
    int pq = rr % 48;

    u64 a[32];
#pragma unroll
    for (int k = 0; k < 32; k++) a[k] = 0ULL;
    u64 xsA = 0ULL, xsB = 0ULL;

    for (int s = 0; s < 16; s++) {
        int n0 = nbase + s*32;
        __syncthreads();
        for (int i = tid; i < CC*32; i += 192) {
            int p = i >> 5, j = i & 31;
            xs[j*196 + p] = x[(size_t)(b*CC + p)*NN + n0 + j];
        }
        for (int i = tid; i < CQ*32; i += 192) {
            int m = i >> 5, j = i & 31;
            float v = g_Kn[(size_t)(b*CQ + m)*NN + n0 + j];
            kst2[j*34 + m] = pk2(v, v);
        }
        __syncthreads();

        int jbeg = jh * 16;
#pragma unroll 2
        for (int jj = 0; jj < 16; jj++) {
            int j = jbeg + jj;
            ulonglong2 xv = *(const ulonglong2*)(xs + j*196 + 4*pq);
            xsA = add2(xsA, xv.x);
            xsB = add2(xsB, xv.y);
            const ulonglong2* kr = (const ulonglong2*)(kst2 + j*34 + mh*16);
#pragma unroll
            for (int mm = 0; mm < 8; mm++) {
                ulonglong2 kk = kr[mm];
                a[mm*4+0] = fma2(kk.x, xv.x, a[mm*4+0]);
                a[mm*4+1] = fma2(kk.x, xv.y, a[mm*4+1]);
                a[mm*4+2] = fma2(kk.y, xv.x, a[mm*4+2]);
                a[mm*4+3] = fma2(kk.y, xv.y, a[mm*4+3]);
            }
        }
    }

    // combine jh halves via smem, then atomics from jh==0
    __syncthreads();
    u64* comb = (u64*)xs;   // 96*32 u64 = 24576 B <= xs size
    int slot = mh*48 + pq;
    if (jh == 1) {
#pragma unroll
        for (int k = 0; k < 32; k++) comb[slot*32 + k] = a[k];
    }
    __syncthreads();
    if (jh == 0) {
#pragma unroll
        for (int k = 0; k < 32; k++) {
            u64 t = add2(a[k], comb[slot*32 + k]);
            float lo, hi; upk2(lo, hi, t);
            int m = mh*16 + ((k >> 2) << 1) + ((k >> 1) & 1);
            int p = 4*pq + ((k & 1) << 1);
            atomicAdd(&g_M1[(b*CQ + m)*CC + p],     lo);
            atomicAdd(&g_M1[(b*CQ + m)*CC + p + 1], hi);
        }
    }
    if (mh == 0) {
        float l0, h0, l1, h1;
        upk2(l0, h0, xsA); upk2(l1, h1, xsB);
        atomicAdd(&g_xsum[b*CC + 4*pq + 0], l0);
        atomicAdd(&g_xsum[b*CC + 4*pq + 1], h0);
        atomicAdd(&g_xsum[b*CC + 4*pq + 2], l1);
        atomicAdd(&g_xsum[b*CC + 4*pq + 3], h1);
    }
}

// ---------------------------------------------------------------------------
// matrix[b,m,c] = sum_p Wv[c,p]*M1[b,m,p] + bv[c]*Ksum[b,m]
// vsum[b,c]    = sum_p Wv[c,p]*xsum[b,p] + N*bv[c]
// grid (BN, 16), block 192 (one thread per c), 12 p per block.
// ---------------------------------------------------------------------------
__global__ void __launch_bounds__(192) mat_kernel(
    const float* __restrict__ Wv, const float* __restrict__ bv)
{
    __shared__ float m1t[CC][36];   // [p][m]
    __shared__ float xs_s[CC];
    int tid = threadIdx.x;
    int b  = blockIdx.x;
    int pg = blockIdx.y;  // 0..15, 12 p's each

    for (int i = tid; i < CQ*CC; i += 192) {
        int m = i / CC, p = i % CC;
        m1t[p][m] = g_M1[b*CQ*CC + i];
    }
    xs_s[tid] = g_xsum[b*CC + tid];
    __syncthreads();

    int c = tid;
    float accm[CQ];
#pragma unroll
    for (int m = 0; m < CQ; m++) accm[m] = 0.f;
    float vs = 0.f;

    for (int p = pg*12; p < (pg+1)*12; p++) {
        float wv = __ldg(&Wv[c*CC + p]);
        vs += wv * xs_s[p];
        const float4* row = (const float4*)&m1t[p][0];
#pragma unroll
        for (int m4 = 0; m4 < 8; m4++) {
            float4 mv = row[m4];
            accm[m4*4+0] += wv*mv.x;
            accm[m4*4+1] += wv*mv.y;
            accm[m4*4+2] += wv*mv.z;
            accm[m4*4+3] += wv*mv.w;
        }
    }
    if (pg == 0) {
        float bvc = __ldg(&bv[c]);
        vs += (float)NN * bvc;
#pragma unroll
        for (int m = 0; m < CQ; m++) accm[m] += bvc * g_Ksum[b*CQ + m];
    }
    atomicAdd(&g_vsum[b*CC + c], vs);
#pragma unroll
    for (int m = 0; m < CQ; m++) atomicAdd(&g_mat[(b*CQ + m)*CC + c], accm[m]);
}

// ---------------------------------------------------------------------------
// out[b,c,n] = gamma*tailor[b,n]*(vsum[b,c] + sum_m Qn[b,m,n]*matrix[b,m,c])
// 4 n per thread (two f32x2 lanes). Block 128, grid (NN/512, BN).
// ---------------------------------------------------------------------------
__global__ void __launch_bounds__(128, 2) final_kernel(
    float* __restrict__ out, const float* __restrict__ gamma)
{
    extern __shared__ u64 smf[];
    u64* mat2 = smf;                 // 192*34
    u64* vs2  = mat2 + 192*34;       // 192
    u64* kse2 = vs2 + 192;           // 32

    int tid = threadIdx.x;
    int b = blockIdx.y;

    for (int i = tid; i < CQ*CC; i += 128) {
        int m = i / CC, c = i % CC;
        float v = g_mat[b*CQ*CC + i];
        mat2[c*34 + m] = pk2(v, v);
    }
    for (int i = tid; i < CC; i += 128) { float v = g_vsum[b*CC + i]; vs2[i] = pk2(v, v); }
    if (tid < CQ) { float v = g_Ksum[b*CQ + tid] + EPSV; kse2[tid] = pk2(v, v); }
    __syncthreads();

    int n0 = (blockIdx.x * 128 + tid) * 4;

    u64 qA[CQ], qB[CQ];   // qA = (n0,n1), qB = (n2,n3)
#pragma unroll
    for (int m = 0; m < CQ; m++) {
        ulonglong2 qq = *(const ulonglong2*)(g_Qn + (size_t)(b*CQ + m)*NN + n0);
        qA[m] = qq.x; qB[m] = qq.y;
    }

    // tailor over all 32 m, 4 chains
    u64 nn2 = pk2((float)NN, (float)NN);
    u64 ta0 = nn2, ta1 = 0ULL, tb0 = nn2, tb1 = 0ULL;
#pragma unroll
    for (int mh = 0; mh < 16; mh++) {
        ulonglong2 ke = ((const ulonglong2*)kse2)[mh];
        ta0 = fma2(qA[2*mh+0], ke.x, ta0);
        ta1 = fma2(qA[2*mh+1], ke.y, ta1);
        tb0 = fma2(qB[2*mh+0], ke.x, tb0);
        tb1 = fma2(qB[2*mh+1], ke.y, tb1);
    }
    u64 tta = add2(ta0, ta1), ttb = add2(tb0, tb1);
    float tl0, th0, tl1, th1;
    upk2(tl0, th0, tta); upk2(tl1, th1, ttb);
    float gm = __ldg(&gamma[0]);
    u64 sA = pk2(gm / tl0, gm / th0);
    u64 sB = pk2(gm / tl1, gm / th1);

    float* op = out + (size_t)(b*CC)*NN + n0;
#pragma unroll 2
    for (int c = 0; c < CC; c++) {
        u64 a0 = vs2[c], a1 = 0ULL, a2 = 0ULL, a3 = 0ULL;
        u64 b0 = vs2[c], b1 = 0ULL, b2 = 0ULL, b3 = 0ULL;
        const ulonglong2* row = (const ulonglong2*)(mat2 + c*34);
#pragma unroll
        for (int m4 = 0; m4 < 8; m4++) {
            ulonglong2 w0 = row[2*m4];
            ulonglong2 w1 = row[2*m4+1];
            a0 = fma2(w0.x, qA[4*m4+0], a0);
            a1 = fma2(w0.y, qA[4*m4+1], a1);
            a2 = fma2(w1.x, qA[4*m4+2], a2);
            a3 = fma2(w1.y, qA[4*m4+3], a3);
            b0 = fma2(w0.x, qB[4*m4+0], b0);
            b1 = fma2(w0.y, qB[4*m4+1], b1);
            b2 = fma2(w1.x, qB[4*m4+2], b2);
            b3 = fma2(w1.y, qB[4*m4+3], b3);
        }
        ulonglong2 res;
        res.x = mul2(add2(add2(a0, a1), add2(a2, a3)), sA);
        res.y = mul2(add2(add2(b0, b1), add2(b2, b3)), sB);
        *(ulonglong2*)(op + (size_t)c*NN) = res;
    }
}

extern "C" void kernel_launch(void* const* d_in, const int* in_sizes, int n_in,
                              void* d_out, int out_size) {
    const float* x     = (const float*)d_in[0];
    const float* x1    = (const float*)d_in[1];
    const float* Wq    = (const float*)d_in[2];
    const float* bq    = (const float*)d_in[3];
    const float* Wk    = (const float*)d_in[4];
    const float* bk    = (const float*)d_in[5];
    const float* Wv    = (const float*)d_in[6];
    const float* bv    = (const float*)d_in[7];
    const float* gamma = (const float*)d_in[8];
    float* out = (float*)d_out;

    const int qk_smem  = CC*68*8;                    // 104448 B
    const int fin_smem = (192*34 + 192 + 32) * 8;    // 54016 B
    cudaFuncSetAttribute(qk_kernel, cudaFuncAttributeMaxDynamicSharedMemorySize, qk_smem);
    cudaFuncSetAttribute(final_kernel, cudaFuncAttributeMaxDynamicSharedMemorySize, fin_smem);

    zero_kernel<<<96, 256>>>();
    qk_kernel<<<dim3(NN/128, BN), 256, qk_smem>>>(x1, Wq, bq, Wk, bk);
    m1_kernel<<<dim3(NN/512, BN), 192>>>(x);
    mat_kernel<<<dim3(BN, 16), 192>>>(Wv, bv);
    final_kernel<<<dim3(NN/512, BN), 128, fin_smem>>>(out, gamma);
}

// round 15
// speedup vs baseline: 1.4459x; 1.4459x over previous
#include <cuda_runtime.h>
#include <cstdint>

#define BN 8
#define CC 192
#define CQ 32
#define NN 16384
#define EPSV 1e-6f

typedef unsigned long long u64;

__device__ __forceinline__ u64 pk2(float lo, float hi) {
    u64 r; asm("mov.b64 %0,{%1,%2};" : "=l"(r) : "f"(lo), "f"(hi)); return r;
}
__device__ __forceinline__ void upk2(float& lo, float& hi, u64 v) {
    asm("mov.b64 {%0,%1},%2;" : "=f"(lo), "=f"(hi) : "l"(v));
}
__device__ __forceinline__ u64 fma2(u64 a, u64 b, u64 c) {
    u64 d; asm("fma.rn.f32x2 %0,%1,%2,%3;" : "=l"(d) : "l"(a), "l"(b), "l"(c)); return d;
}
__device__ __forceinline__ u64 mul2(u64 a, u64 b) {
    u64 d; asm("mul.rn.f32x2 %0,%1,%2;" : "=l"(d) : "l"(a), "l"(b)); return d;
}
__device__ __forceinline__ u64 add2(u64 a, u64 b) {
    u64 d; asm("add.rn.f32x2 %0,%1,%2;" : "=l"(d) : "l"(a), "l"(b)); return d;
}

__device__ __forceinline__ float to_tf32(float v) {
    float r; asm("cvt.rna.tf32.f32 %0, %1;" : "=f"(r) : "f"(v)); return r;
}

// D(16x8) += A(16x8,row) * B(8x8,col), tf32 inputs (b32 regs), f32 accum.
__device__ __forceinline__ void mma_tf32(float* d, const uint32_t* a,
                                         const uint32_t* b) {
    asm volatile(
        "mma.sync.aligned.m16n8k8.row.col.f32.tf32.tf32.f32 "
        "{%0,%1,%2,%3}, {%4,%5,%6,%7}, {%8,%9}, {%0,%1,%2,%3};"
        : "+f"(d[0]), "+f"(d[1]), "+f"(d[2]), "+f"(d[3])
        : "r"(a[0]), "r"(a[1]), "r"(a[2]), "r"(a[3]), "r"(b[0]), "r"(b[1]));
}

// Scratch (device globals: no allocation allowed)
__device__ float g_Qn[BN*CQ*NN];
__device__ float g_Kn[BN*CQ*NN];
__device__ float g_Ksum[BN*CQ];
__device__ float g_xsum[BN*CC];
__device__ float g_M1[BN*CQ*CC];
__device__ float g_mat[BN*CQ*CC];
__device__ float g_vsum[BN*CC];

__global__ void zero_kernel() {
    int i = blockIdx.x * blockDim.x + threadIdx.x;
    int stride = gridDim.x * blockDim.x;
    for (int j = i; j < BN*CQ; j += stride) g_Ksum[j] = 0.f;
    for (int j = i; j < BN*CC; j += stride) { g_xsum[j] = 0.f; g_vsum[j] = 0.f; }
    for (int j = i; j < BN*CQ*CC; j += stride) { g_M1[j] = 0.f; g_mat[j] = 0.f; }
}

// ---------------------------------------------------------------------------
// Q/K projection + L2 norm via mma.sync tf32 (3-term split, ~fp32 accurate).
// (unchanged from R11 — measured good)
// ---------------------------------------------------------------------------
__global__ void __launch_bounds__(256, 1) qk_kernel(
    const float* __restrict__ x1,
    const float* __restrict__ Wq, const float* __restrict__ bq,
    const float* __restrict__ Wk, const float* __restrict__ bk)
{
    extern __shared__ uint2 whl[];   // [192][68] row-pitch, entries {hi,lo}

    int tid = threadIdx.x;
    int bb  = blockIdx.y;
    int nb  = blockIdx.x * 128;

    for (int i = tid; i < 64*CC; i += 256) {
        int row = i / CC, k = i % CC;
        float w = (row < CQ) ? Wq[row*CC + k] : Wk[(row-CQ)*CC + k];
        float hi = to_tf32(w);
        float lo = to_tf32(w - hi);
        whl[k*68 + row] = make_uint2(__float_as_uint(hi), __float_as_uint(lo));
    }
    __syncthreads();

    int w  = tid >> 5;
    int ln = tid & 31;
    int g  = ln >> 2;
    int la = ln & 3;
    int nwarp = nb + w*16;

    float d[2][4][4];
#pragma unroll
    for (int s = 0; s < 2; s++)
#pragma unroll
        for (int t = 0; t < 4; t++)
#pragma unroll
            for (int j = 0; j < 4; j++) d[s][t][j] = 0.f;

    const float* xbase = x1 + (size_t)(bb*CC)*NN + nwarp + g;

    float cb0[2], cb1[2];
#pragma unroll
    for (int s = 0; s < 2; s++) {
        const float* xp = xbase + (size_t)la*NN + s*8;
        cb0[s] = xp[0];
        cb1[s] = xp[(size_t)4*NN];
    }

    for (int ks = 0; ks < 24; ks++) {
        int k0 = ks*8;
        float nb0[2], nb1[2];
        if (ks + 1 < 24) {
            const float* xr = xbase + (size_t)(k0 + 8 + la)*NN;
#pragma unroll
            for (int s = 0; s < 2; s++) {
                nb0[s] = xr[s*8];
                nb1[s] = xr[(size_t)4*NN + s*8];
            }
        }

        uint32_t ahi[4][4], alo[4][4];
#pragma unroll
        for (int t = 0; t < 4; t++) {
            int r0 = g + 16*t, r1 = r0 + 8;
            uint2 v0 = whl[(k0+la)*68 + r0];
            uint2 v1 = whl[(k0+la)*68 + r1];
            uint2 v2 = whl[(k0+la+4)*68 + r0];
            uint2 v3 = whl[(k0+la+4)*68 + r1];
            ahi[t][0] = v0.x; alo[t][0] = v0.y;
            ahi[t][1] = v1.x; alo[t][1] = v1.y;
            ahi[t][2] = v2.x; alo[t][2] = v2.y;
            ahi[t][3] = v3.x; alo[t][3] = v3.y;
        }

#pragma unroll
        for (int s = 0; s < 2; s++) {
            float h0 = to_tf32(cb0[s]), l0f = to_tf32(cb0[s] - h0);
            float h1 = to_tf32(cb1[s]), l1f = to_tf32(cb1[s] - h1);
            uint32_t bh[2] = { __float_as_uint(h0), __float_as_uint(h1) };
            uint32_t bl[2] = { __float_as_uint(l0f), __float_as_uint(l1f) };
#pragma unroll
            for (int t = 0; t < 4; t++) {
                mma_tf32(d[s][t], ahi[t], bh);
                mma_tf32(d[s][t], alo[t], bh);
                mma_tf32(d[s][t], ahi[t], bl);
            }
        }
#pragma unroll
        for (int s = 0; s < 2; s++) { cb0[s] = nb0[s]; cb1[s] = nb1[s]; }
    }

#pragma unroll
    for (int t = 0; t < 4; t++) {
        int r0 = g + 16*t, r1 = r0 + 8;
        float bias0 = (r0 < CQ) ? __ldg(&bq[r0]) : __ldg(&bk[r0-CQ]);
        float bias1 = (r1 < CQ) ? __ldg(&bq[r1]) : __ldg(&bk[r1-CQ]);
#pragma unroll
        for (int s = 0; s < 2; s++) {
            d[s][t][0] += bias0; d[s][t][1] += bias0;
            d[s][t][2] += bias1; d[s][t][3] += bias1;
        }
    }

    float qs0[2], qs1[2], ks0[2], ks1[2];
#pragma unroll
    for (int s = 0; s < 2; s++) {
        qs0[s] = d[s][0][0]*d[s][0][0] + d[s][0][2]*d[s][0][2]
               + d[s][1][0]*d[s][1][0] + d[s][1][2]*d[s][1][2];
        qs1[s] = d[s][0][1]*d[s][0][1] + d[s][0][3]*d[s][0][3]
               + d[s][1][1]*d[s][1][1] + d[s][1][3]*d[s][1][3];
        ks0[s] = d[s][2][0]*d[s][2][0] + d[s][2][2]*d[s][2][2]
               + d[s][3][0]*d[s][3][0] + d[s][3][2]*d[s][3][2];
        ks1[s] = d[s][2][1]*d[s][2][1] + d[s][2][3]*d[s][2][3]
               + d[s][3][1]*d[s][3][1] + d[s][3][3]*d[s][3][3];
    }
#pragma unroll
    for (int o = 4; o <= 16; o <<= 1) {
#pragma unroll
        for (int s = 0; s < 2; s++) {
            qs0[s] += __shfl_xor_sync(0xffffffffu, qs0[s], o);
            qs1[s] += __shfl_xor_sync(0xffffffffu, qs1[s], o);
            ks0[s] += __shfl_xor_sync(0xffffffffu, ks0[s], o);
            ks1[s] += __shfl_xor_sync(0xffffffffu, ks1[s], o);
        }
    }

    float krow[4];
#pragma unroll
    for (int j = 0; j < 4; j++) krow[j] = 0.f;

#pragma unroll
    for (int s = 0; s < 2; s++) {
        float iq0 = rsqrtf(qs0[s]), iq1 = rsqrtf(qs1[s]);
        float ik0 = rsqrtf(ks0[s]), ik1 = rsqrtf(ks1[s]);
        int ncol = nwarp + s*8 + la*2;
#pragma unroll
        for (int t = 0; t < 2; t++) {
            int m = g + 16*t;
            float2 v0 = make_float2(d[s][t][0]*iq0, d[s][t][1]*iq1);
            float2 v1 = make_float2(d[s][t][2]*iq0, d[s][t][3]*iq1);
            *(float2*)(g_Qn + (size_t)(bb*CQ + m)*NN + ncol)     = v0;
            *(float2*)(g_Qn + (size_t)(bb*CQ + m + 8)*NN + ncol) = v1;
        }
#pragma unroll
        for (int t = 2; t < 4; t++) {
            int m = g + 16*(t-2);
            float c0 = d[s][t][0]*ik0, c1 = d[s][t][1]*ik1;
            float c2 = d[s][t][2]*ik0, c3 = d[s][t][3]*ik1;
            *(float2*)(g_Kn + (size_t)(bb*CQ + m)*NN + ncol)     = make_float2(c0, c1);
            *(float2*)(g_Kn + (size_t)(bb*CQ + m + 8)*NN + ncol) = make_float2(c2, c3);
            krow[(t-2)*2]   += c0 + c1;
            krow[(t-2)*2+1] += c2 + c3;
        }
    }
#pragma unroll
    for (int o = 1; o <= 2; o <<= 1)
#pragma unroll
        for (int j = 0; j < 4; j++)
            krow[j] += __shfl_xor_sync(0xffffffffu, krow[j], o);
    if (la == 0) {
        atomicAdd(&g_Ksum[bb*CQ + g],      krow[0]);
        atomicAdd(&g_Ksum[bb*CQ + g + 8],  krow[1]);
        atomicAdd(&g_Ksum[bb*CQ + g + 16], krow[2]);
        atomicAdd(&g_Ksum[bb*CQ + g + 24], krow[3]);
    }
}

// ---------------------------------------------------------------------------
// M1[b,m,p] = sum_n Kn[b,m,n]*x[b,p,n] via mma.sync tf32 (3-term split).
// A = Kn (M=32, 2 tiles), B[k=n][col=p] = x (x's layout IS the col-major B
// fragment). No smem: A from g_Kn via __ldg (L1-resident), B from x (each
// element read once per chip). xsum folded from raw B values.
// Block 256 = 8 warps; warp w owns p in [w*24, w*24+24) (3 N-tiles).
// Grid (NN/512, BN): each block reduces a 512-n chunk, atomics into g_M1.
// ---------------------------------------------------------------------------
__global__ void __launch_bounds__(256) m1_kernel(const float* __restrict__ x)
{
    int tid = threadIdx.x;
    int b = blockIdx.y;
    int w = tid >> 5, ln = tid & 31;
    int g = ln >> 2, la = ln & 3;
    int p0 = w * 24;
    int nchunk = blockIdx.x * 512;

    const float* kb = g_Kn + (size_t)(b*CQ)*NN + nchunk + la;
    const float* xb = x + (size_t)(b*CC + p0)*NN + nchunk + la;

    float d[2][3][4];
#pragma unroll
    for (int t = 0; t < 2; t++)
#pragma unroll
        for (int u = 0; u < 3; u++)
#pragma unroll
            for (int j = 0; j < 4; j++) d[t][u][j] = 0.f;
    float xs[3] = {0.f, 0.f, 0.f};

#pragma unroll 2
    for (int ks = 0; ks < 64; ks++) {
        int k0 = ks * 8;

        uint32_t ahi[2][4], alo[2][4];
#pragma unroll
        for (int t = 0; t < 2; t++) {
            const float* kr0 = kb + (size_t)(16*t + g)*NN + k0;
            const float* kr1 = kb + (size_t)(16*t + g + 8)*NN + k0;
            float v0 = __ldg(kr0),     v1 = __ldg(kr1);
            float v2 = __ldg(kr0 + 4), v3 = __ldg(kr1 + 4);
            float h;
            h = to_tf32(v0); ahi[t][0] = __float_as_uint(h); alo[t][0] = __float_as_uint(to_tf32(v0 - h));
            h = to_tf32(v1); ahi[t][1] = __float_as_uint(h); alo[t][1] = __float_as_uint(to_tf32(v1 - h));
            h = to_tf32(v2); ahi[t][2] = __float_as_uint(h); alo[t][2] = __float_as_uint(to_tf32(v2 - h));
            h = to_tf32(v3); ahi[t][3] = __float_as_uint(h); alo[t][3] = __float_as_uint(to_tf32(v3 - h));
        }

#pragma unroll
        for (int u = 0; u < 3; u++) {
            const float* xr = xb + (size_t)(u*8 + g)*NN + k0;
            float x0 = __ldg(xr), x1 = __ldg(xr + 4);
            xs[u] += x0 + x1;
            float h0 = to_tf32(x0), h1 = to_tf32(x1);
            uint32_t bh[2] = { __float_as_uint(h0), __float_as_uint(h1) };
            uint32_t bl[2] = { __float_as_uint(to_tf32(x0 - h0)),
                               __float_as_uint(to_tf32(x1 - h1)) };
#pragma unroll
            for (int t = 0; t < 2; t++) {
                mma_tf32(d[t][u], ahi[t], bh);
                mma_tf32(d[t][u], alo[t], bh);
                mma_tf32(d[t][u], ahi[t], bl);
            }
        }
    }

    // xsum: lanes within a group (la = 0..3) hold disjoint n-positions of row p
#pragma unroll
    for (int u = 0; u < 3; u++) {
        float s = xs[u];
        s += __shfl_xor_sync(0xffffffffu, s, 1);
        s += __shfl_xor_sync(0xffffffffu, s, 2);
        if (la == 0) atomicAdd(&g_xsum[b*CC + p0 + u*8 + g], s);
    }

    // M1 atomics: d0=(row, col), d1=(row, col+1), d2=(row+8, col), d3=(row+8, col+1)
#pragma unroll
    for (int t = 0; t < 2; t++) {
#pragma unroll
        for (int u = 0; u < 3; u++) {
            int m0 = 16*t + g;
            int pc = p0 + u*8 + la*2;
            float* base = g_M1 + (size_t)(b*CQ + m0)*CC + pc;
            atomicAdd(base,            d[t][u][0]);
            atomicAdd(base + 1,        d[t][u][1]);
            atomicAdd(base + 8*CC,     d[t][u][2]);
            atomicAdd(base + 8*CC + 1, d[t][u][3]);
        }
    }
}

// ---------------------------------------------------------------------------
// matrix[b,m,c] = sum_p Wv[c,p]*M1[b,m,p] + bv[c]*Ksum[b,m]
// vsum[b,c]    = sum_p Wv[c,p]*xsum[b,p] + N*bv[c]
// grid (BN, 16), block 192 (one thread per c), 12 p per block.
// ---------------------------------------------------------------------------
__global__ void __launch_bounds__(192) mat_kernel(
    const float* __restrict__ Wv, const float* __restrict__ bv)
{
    __shared__ float m1t[CC][36];   // [p][m]
    __shared__ float xs_s[CC];
    int tid = threadIdx.x;
    int b  = blockIdx.x;
    int pg = blockIdx.y;  // 0..15, 12 p's each

    for (int i = tid; i < CQ*CC; i += 192) {
        int m = i / CC, p = i % CC;
        m1t[p][m] = g_M1[b*CQ*CC + i];
    }
    xs_s[tid] = g_xsum[b*CC + tid];
    __syncthreads();

    int c = tid;
    float accm[CQ];
#pragma unroll
    for (int m = 0; m < CQ; m++) accm[m] = 0.f;
    float vs = 0.f;

    for (int p = pg*12; p < (pg+1)*12; p++) {
        float wv = __ldg(&Wv[c*CC + p]);
        vs += wv * xs_s[p];
        const float4* row = (const float4*)&m1t[p][0];
#pragma unroll
        for (int m4 = 0; m4 < 8; m4++) {
            float4 mv = row[m4];
            accm[m4*4+0] += wv*mv.x;
            accm[m4*4+1] += wv*mv.y;
            accm[m4*4+2] += wv*mv.z;
            accm[m4*4+3] += wv*mv.w;
        }
    }
    if (pg == 0) {
        float bvc = __ldg(&bv[c]);
        vs += (float)NN * bvc;
#pragma unroll
        for (int m = 0; m < CQ; m++) accm[m] += bvc * g_Ksum[b*CQ + m];
    }
    atomicAdd(&g_vsum[b*CC + c], vs);
#pragma unroll
    for (int m = 0; m < CQ; m++) atomicAdd(&g_mat[(b*CQ + m)*CC + c], accm[m]);
}

// ---------------------------------------------------------------------------
// out[b,c,n] = gamma*tailor[b,n]*(vsum[b,c] + sum_m Qn[b,m,n]*matrix[b,m,c])
// 4 n per thread (two f32x2 lanes). Block 128, grid (NN/512, BN).
// ---------------------------------------------------------------------------
__global__ void __launch_bounds__(128, 2) final_kernel(
    float* __restrict__ out, const float* __restrict__ gamma)
{
    extern __shared__ u64 smf[];
    u64* mat2 = smf;                 // 192*34
    u64* vs2  = mat2 + 192*34;       // 192
    u64* kse2 = vs2 + 192;           // 32

    int tid = threadIdx.x;
    int b = blockIdx.y;

    for (int i = tid; i < CQ*CC; i += 128) {
        int m = i / CC, c = i % CC;
        float v = g_mat[b*CQ*CC + i];
        mat2[c*34 + m] = pk2(v, v);
    }
    for (int i = tid; i < CC; i += 128) { float v = g_vsum[b*CC + i]; vs2[i] = pk2(v, v); }
    if (tid < CQ) { float v = g_Ksum[b*CQ + tid] + EPSV; kse2[tid] = pk2(v, v); }
    __syncthreads();

    int n0 = (blockIdx.x * 128 + tid) * 4;

    u64 qA[CQ], qB[CQ];
#pragma unroll
    for (int m = 0; m < CQ; m++) {
        ulonglong2 qq = *(const ulonglong2*)(g_Qn + (size_t)(b*CQ + m)*NN + n0);
        qA[m] = qq.x; qB[m] = qq.y;
    }

    u64 nn2 = pk2((float)NN, (float)NN);
    u64 ta0 = nn2, ta1 = 0ULL, tb0 = nn2, tb1 = 0ULL;
#pragma unroll
    for (int mh = 0; mh < 16; mh++) {
        ulonglong2 ke = ((const ulonglong2*)kse2)[mh];
        ta0 = fma2(qA[2*mh+0], ke.x, ta0);
        ta1 = fma2(qA[2*mh+1], ke.y, ta1);
        tb0 = fma2(qB[2*mh+0], ke.x, tb0);
        tb1 = fma2(qB[2*mh+1], ke.y, tb1);
    }
    u64 tta = add2(ta0, ta1), ttb = add2(tb0, tb1);
    float tl0, th0, tl1, th1;
    upk2(tl0, th0, tta); upk2(tl1, th1, ttb);
    float gm = __ldg(&gamma[0]);
    u64 sA = pk2(gm / tl0, gm / th0);
    u64 sB = pk2(gm / tl1, gm / th1);

    float* op = out + (size_t)(b*CC)*NN + n0;
#pragma unroll 2
    for (int c = 0; c < CC; c++) {
        u64 a0 = vs2[c], a1 = 0ULL, a2 = 0ULL, a3 = 0ULL;
        u64 b0 = vs2[c], b1 = 0ULL, b2 = 0ULL, b3 = 0ULL;
        const ulonglong2* row = (const ulonglong2*)(mat2 + c*34);
#pragma unroll
        for (int m4 = 0; m4 < 8; m4++) {
            ulonglong2 w0 = row[2*m4];
            ulonglong2 w1 = row[2*m4+1];
            a0 = fma2(w0.x, qA[4*m4+0], a0);
            a1 = fma2(w0.y, qA[4*m4+1], a1);
            a2 = fma2(w1.x, qA[4*m4+2], a2);
            a3 = fma2(w1.y, qA[4*m4+3], a3);
            b0 = fma2(w0.x, qB[4*m4+0], b0);
            b1 = fma2(w0.y, qB[4*m4+1], b1);
            b2 = fma2(w1.x, qB[4*m4+2], b2);
            b3 = fma2(w1.y, qB[4*m4+3], b3);
        }
        ulonglong2 res;
        res.x = mul2(add2(add2(a0, a1), add2(a2, a3)), sA);
        res.y = mul2(add2(add2(b0, b1), add2(b2, b3)), sB);
        *(ulonglong2*)(op + (size_t)c*NN) = res;
    }
}

extern "C" void kernel_launch(void* const* d_in, const int* in_sizes, int n_in,
                              void* d_out, int out_size) {
    const float* x     = (const float*)d_in[0];
    const float* x1    = (const float*)d_in[1];
    const float* Wq    = (const float*)d_in[2];
    const float* bq    = (const float*)d_in[3];
    const float* Wk    = (const float*)d_in[4];
    const float* bk    = (const float*)d_in[5];
    const float* Wv    = (const float*)d_in[6];
    const float* bv    = (const float*)d_in[7];
    const float* gamma = (const float*)d_in[8];
    float* out = (float*)d_out;

    const int qk_smem  = CC*68*8;                    // 104448 B
    const int fin_smem = (192*34 + 192 + 32) * 8;    // 54016 B
    cudaFuncSetAttribute(qk_kernel, cudaFuncAttributeMaxDynamicSharedMemorySize, qk_smem);
    cudaFuncSetAttribute(final_kernel, cudaFuncAttributeMaxDynamicSharedMemorySize, fin_smem);

    zero_kernel<<<96, 256>>>();
    qk_kernel<<<dim3(NN/128, BN), 256, qk_smem>>>(x1, Wq, bq, Wk, bk);
    m1_kernel<<<dim3(NN/512, BN), 256>>>(x);
    mat_kernel<<<dim3(BN, 16), 192>>>(Wv, bv);
    final_kernel<<<dim3(NN/512, BN), 128, fin_smem>>>(out, gamma);
}